// round 3
// baseline (speedup 1.0000x reference)
#include <cuda_runtime.h>
#include <cuda_fp16.h>
#include <cstdint>

// MonarchLayer: y[b, l*64+j] = sum_k L[j,k,l] * t1[b,k,j] + bias,
//               t1[b,k,j]    = sum_i x[b,k*64+i] * R[k,i,j]
// Two-stage tensor-core (HMMA m16n8k16, fp16 in / fp32 acc) implementation with
// an fp16 global intermediate. Inputs (metadata order): x, L, R, bias. Output f32.

#define BATCH 16384
#define DIMN  4096
#define MBLK  64

// ---------------- device scratch (static, allocation-free) ----------------
__device__ __align__(16) __half g_T1[(size_t)BATCH * DIMN];  // 128 MB fp16 intermediate
__device__ __align__(16) __half g_Rh[64 * 64 * 64];          // R cast to fp16 [k][i][j]
__device__ __align__(16) __half g_Lh[64 * 64 * 64];          // L cast to fp16 [j][k][l]

// ---------------- helpers ----------------
__device__ __forceinline__ uint32_t smem_u32(const void* p) {
    uint32_t a;
    asm("{ .reg .u64 t; cvta.to.shared.u64 t, %1; cvt.u32.u64 %0, t; }" : "=r"(a) : "l"(p));
    return a;
}
// XOR swizzle inside a tile with 128-byte rows, 16B granularity: conflict-free
// for both the ldmatrix loads and the staging stores.
__device__ __forceinline__ int swz(int row, int chunk) {
    return row * 128 + (((chunk) ^ (row & 7)) << 4);
}
__device__ __forceinline__ void ldm_x4(uint32_t* r, uint32_t addr) {
    asm volatile("ldmatrix.sync.aligned.m8n8.x4.shared.b16 {%0,%1,%2,%3}, [%4];"
                 : "=r"(r[0]), "=r"(r[1]), "=r"(r[2]), "=r"(r[3]) : "r"(addr));
}
__device__ __forceinline__ void ldm_x2t(uint32_t* r, uint32_t addr) {
    asm volatile("ldmatrix.sync.aligned.m8n8.x2.trans.shared.b16 {%0,%1}, [%2];"
                 : "=r"(r[0]), "=r"(r[1]) : "r"(addr));
}
__device__ __forceinline__ void mma16816(float* c, const uint32_t* a, const uint32_t* b) {
    asm volatile("mma.sync.aligned.m16n8k16.row.col.f32.f16.f16.f32 "
                 "{%0,%1,%2,%3}, {%4,%5,%6,%7}, {%8,%9}, {%0,%1,%2,%3};"
                 : "+f"(c[0]), "+f"(c[1]), "+f"(c[2]), "+f"(c[3])
                 : "r"(a[0]), "r"(a[1]), "r"(a[2]), "r"(a[3]), "r"(b[0]), "r"(b[1]));
}

// ---------------- prep: cast L,R to fp16 ----------------
__global__ void monarch_prep(const float* __restrict__ L, const float* __restrict__ R) {
    int idx = blockIdx.x * blockDim.x + threadIdx.x;
    if (idx < 64 * 64 * 64) {
        g_Rh[idx] = __float2half_rn(R[idx]);  // [k][i][j] direct cast
        g_Lh[idx] = __float2half_rn(L[idx]);  // [j][k][l] direct cast
    }
}

// ---------------- stage 1: T1[b, k*64+j] = sum_i x[b,k*64+i] * R[k,i,j] ----------------
// grid: (64 k-blocks, 128 batch tiles), 256 threads, batch tile = 128 rows.
__global__ __launch_bounds__(256) void monarch_k1(const float* __restrict__ x) {
    __shared__ __align__(16) unsigned char sA[128 * 128];  // 128x64 fp16 A tile (swizzled)
    __shared__ __align__(16) unsigned char sB[64 * 128];   // 64x64 fp16 R_k tile (swizzled)

    const int kblk = blockIdx.x;
    const size_t b0 = (size_t)blockIdx.y * 128;
    const int tid = threadIdx.x;

    // Load + convert X tile: 1024 chunks of 8 halfs (from 8 floats)
#pragma unroll
    for (int i = 0; i < 4; i++) {
        int cid = tid + i * 256;
        int r = cid >> 3, c = cid & 7;
        const float4* gp = (const float4*)(x + (b0 + r) * DIMN + kblk * 64 + c * 8);
        float4 f0 = gp[0], f1 = gp[1];
        uint4 pk;
        __half2* hp = (__half2*)&pk;
        hp[0] = __floats2half2_rn(f0.x, f0.y);
        hp[1] = __floats2half2_rn(f0.z, f0.w);
        hp[2] = __floats2half2_rn(f1.x, f1.y);
        hp[3] = __floats2half2_rn(f1.z, f1.w);
        *(uint4*)(sA + swz(r, c)) = pk;
    }
    // Load R_k tile (fp16, already converted): 512 chunks
#pragma unroll
    for (int i = 0; i < 2; i++) {
        int cid = tid + i * 256;
        int r = cid >> 3, c = cid & 7;
        uint4 v = *(const uint4*)(g_Rh + kblk * 4096 + r * 64 + c * 8);
        *(uint4*)(sB + swz(r, c)) = v;
    }
    __syncthreads();

    const int w = tid >> 5, lane = tid & 31;
    const int rbase = w << 4;  // 8 warps x 16 rows
    const uint32_t sa = smem_u32(sA), sb = smem_u32(sB);

    float acc[8][4];
#pragma unroll
    for (int nt = 0; nt < 8; nt++)
#pragma unroll
        for (int c = 0; c < 4; c++) acc[nt][c] = 0.f;

#pragma unroll
    for (int kk = 0; kk < 4; kk++) {
        uint32_t a[4];
        {
            int row = rbase + ((lane >> 3) & 1) * 8 + (lane & 7);
            int ch = 2 * kk + (lane >> 4);
            ldm_x4(a, sa + swz(row, ch));
        }
#pragma unroll
        for (int nt = 0; nt < 8; nt++) {
            uint32_t bf[2];
            int row = kk * 16 + (lane & 15);
            ldm_x2t(bf, sb + swz(row, nt));
            mma16816(acc[nt], a, bf);
        }
    }
    __syncthreads();  // A tile no longer needed; reuse as output staging

    const int gr = lane >> 2, q = lane & 3;
#pragma unroll
    for (int nt = 0; nt < 8; nt++) {
        int r0 = rbase + gr, r1 = r0 + 8;
        *(__half2*)(sA + swz(r0, nt) + q * 4) = __floats2half2_rn(acc[nt][0], acc[nt][1]);
        *(__half2*)(sA + swz(r1, nt) + q * 4) = __floats2half2_rn(acc[nt][2], acc[nt][3]);
    }
    __syncthreads();

    // Flush to global T1 (natural layout, fully coalesced 16B stores)
#pragma unroll
    for (int i = 0; i < 4; i++) {
        int cid = tid + i * 256;
        int r = cid >> 3, c = cid & 7;
        uint4 v = *(uint4*)(sA + swz(r, c));
        *(uint4*)(g_T1 + (b0 + r) * DIMN + kblk * 64 + c * 8) = v;
    }
}

// ---------------- stage 2: y[b, l*64+j] = sum_k T1[b,k*64+j] * L[j,k,l] + bias ----------------
// grid: (8 j-groups, 256 batch tiles), 256 threads, batch tile = 64 rows, 8 j per CTA.
// Dynamic smem: 64KB A planes (8 x 64x64 fp16) + 64KB L planes (8 x 64x64 fp16) = 128KB.
__global__ __launch_bounds__(256) void monarch_k2(float* __restrict__ out,
                                                  const float* __restrict__ bias) {
    extern __shared__ unsigned char smem[];
    unsigned char* sA = smem;           // 8 planes * 8192 B
    unsigned char* sL = smem + 65536;   // 8 planes * 8192 B

    const int jg = blockIdx.x;
    const int b0 = blockIdx.y * 64;
    const int tid = threadIdx.x;

    // Load 8 L[j] tiles (contiguous, coalesced)
#pragma unroll
    for (int i = 0; i < 16; i++) {
        int idx = tid + i * 256;          // 0..4095 chunks
        int p = idx >> 9, wi = idx & 511;
        int r = wi >> 3, c = wi & 7;
        uint4 v = *(const uint4*)(g_Lh + (size_t)(jg * 8 + p) * 4096 + r * 64 + c * 8);
        *(uint4*)(sL + p * 8192 + swz(r, c)) = v;
    }
    // Gather T1 columns: per (row, k-pair) load 2x16B (8 j's each), scatter half2 to 8 planes
#pragma unroll
    for (int i = 0; i < 8; i++) {
        int idx = tid + i * 256;          // 0..2047
        int r = idx >> 5, kp = idx & 31;
        int kc = kp * 2;
        const __half* gp = g_T1 + (size_t)(b0 + r) * DIMN + kc * 64 + jg * 8;
        uint4 v0 = *(const uint4*)gp;
        uint4 v1 = *(const uint4*)(gp + 64);
        const __half* h0 = (const __half*)&v0;
        const __half* h1 = (const __half*)&v1;
        int ch = kc >> 3, off = (kc & 7) * 2;
#pragma unroll
        for (int s = 0; s < 8; s++) {
            *(__half2*)(sA + s * 8192 + swz(r, ch) + off) = __halves2half2(h0[s], h1[s]);
        }
    }
    __syncthreads();

    const int w = tid >> 5, lane = tid & 31;
    const int rbase = (w & 3) << 4;   // 4 row strips of 16
    const int ntbase = (w >> 2) << 2; // 2 l-halves of 4 n-tiles
    const int gr = lane >> 2, q = lane & 3;
    const uint32_t sa32 = smem_u32(sA), sl32 = smem_u32(sL);

    float st[4][4][8];  // [ntile][frag][j] kept in registers

#pragma unroll
    for (int j = 0; j < 8; j++) {
        uint32_t pa = sa32 + j * 8192;
        uint32_t pb = sl32 + j * 8192;
        uint32_t a[4][4];
#pragma unroll
        for (int kk = 0; kk < 4; kk++) {
            int row = rbase + ((lane >> 3) & 1) * 8 + (lane & 7);
            int ch = 2 * kk + (lane >> 4);
            ldm_x4(a[kk], pa + swz(row, ch));
        }
#pragma unroll
        for (int n = 0; n < 4; n++) {
            int nt = ntbase + n;
            float acc[4] = {0.f, 0.f, 0.f, 0.f};
#pragma unroll
            for (int kk = 0; kk < 4; kk++) {
                uint32_t bf[2];
                int row = kk * 16 + (lane & 15);
                ldm_x2t(bf, pb + swz(row, nt));
                mma16816(acc, a[kk], bf);
            }
            st[n][0][j] = acc[0];
            st[n][1][j] = acc[1];
            st[n][2][j] = acc[2];
            st[n][3][j] = acc[3];
        }
    }

    // Epilogue: each thread owns 8 consecutive output floats per position -> 2x float4
#pragma unroll
    for (int n = 0; n < 4; n++) {
        int nt = ntbase + n;
#pragma unroll
        for (int ci = 0; ci < 4; ci++) {
            int roff = (ci & 2) ? 8 : 0;
            int l = nt * 8 + q * 2 + (ci & 1);
            int row = b0 + rbase + gr + roff;
            const float* bp = bias + l * 64 + jg * 8;
            float4 blo = *(const float4*)bp;
            float4 bhi = *(const float4*)(bp + 4);
            float4 lo = make_float4(st[n][ci][0] + blo.x, st[n][ci][1] + blo.y,
                                    st[n][ci][2] + blo.z, st[n][ci][3] + blo.w);
            float4 hi = make_float4(st[n][ci][4] + bhi.x, st[n][ci][5] + bhi.y,
                                    st[n][ci][6] + bhi.z, st[n][ci][7] + bhi.w);
            float* op = out + (size_t)row * DIMN + l * 64 + jg * 8;
            *(float4*)op = lo;
            *(float4*)(op + 4) = hi;
        }
    }
}

// ---------------- launch ----------------
extern "C" void kernel_launch(void* const* d_in, const int* in_sizes, int n_in,
                              void* d_out, int out_size) {
    (void)in_sizes; (void)n_in; (void)out_size;
    const float* x    = (const float*)d_in[0];
    const float* L    = (const float*)d_in[1];
    const float* R    = (const float*)d_in[2];
    const float* bias = (const float*)d_in[3];
    float* out = (float*)d_out;

    cudaFuncSetAttribute(monarch_k2, cudaFuncAttributeMaxDynamicSharedMemorySize, 131072);

    monarch_prep<<<1024, 256>>>(L, R);
    monarch_k1<<<dim3(64, 128), 256>>>(x);
    monarch_k2<<<dim3(8, 256), 256, 131072>>>(out, bias);
}